// round 7
// baseline (speedup 1.0000x reference)
#include <cuda_runtime.h>

#define D 64
#define MAX_NODES 150016
#define BUCKET 64            // per-dst capacity; max degree (Poisson mean 13.3) << 64
#define BSHIFT 6

// Static scratch (allocation-free rule). Kernels bind these symbols directly;
// never passed from host as kernel args (host-side decay bug, R4).
__device__ float g_x[(size_t)MAX_NODES * D];          // x0 concat, later x2
__device__ float g_y[(size_t)MAX_NODES * D];          // x1
__device__ float g_b3[(size_t)MAX_NODES * D];         // x3 (sampled rows only)
__device__ int   g_cnt[MAX_NODES];                    // per-dst edge counts
__device__ int2  g_edge[(size_t)MAX_NODES * BUCKET];  // bucketed (src, w-bits)

// Concatenate user/item embeddings into g_x (x0) and zero the bucket counts.
__global__ void init_kernel(const float* __restrict__ ue,
                            const float* __restrict__ ie,
                            int n_user_f, int n4, int n_nodes) {
    int i = blockIdx.x * blockDim.x + threadIdx.x;   // float4 index
    if (i < n_nodes) g_cnt[i] = 0;
    if (i >= n4) return;
    int f = i << 2;
    float4 v = (f < n_user_f) ? ((const float4*)ue)[i]
                              : ((const float4*)ie)[i - (n_user_f >> 2)];
    ((float4*)g_x)[i] = v;
}

// One-pass edge bucketing: pos = cnt[dst]++, bucket[dst*64+pos] = (src, w).
__global__ void bucket_kernel(const int* __restrict__ src,
                              const int* __restrict__ dst,
                              const float* __restrict__ w, int n_edges) {
    int e = blockIdx.x * blockDim.x + threadIdx.x;
    if (e >= n_edges) return;
    int d = dst[e];
    int pos = atomicAdd(&g_cnt[d], 1);
    if (pos < BUCKET)   // guard (never taken for this fixed input)
        g_edge[((size_t)d << BSHIFT) + pos] = make_int2(src[e], __float_as_int(w[e]));
}

// Row-gather accumulate for one (node, c) slice over the node's bucket.
__device__ __forceinline__ float4 row_gather(const float* __restrict__ x,
                                             int node, int c) {
    size_t beg = (size_t)node << BSHIFT;
    int cnt = g_cnt[node];
    if (cnt > BUCKET) cnt = BUCKET;
    size_t end = beg + cnt;
    float4 a = make_float4(0.f, 0.f, 0.f, 0.f);
    size_t i = beg;
    for (; i + 2 <= end; i += 2) {         // 2x unroll for gather MLP
        int2 p0 = g_edge[i];
        int2 p1 = g_edge[i + 1];
        float4 v0 = *(const float4*)(x + (size_t)p0.x * D + c);
        float4 v1 = *(const float4*)(x + (size_t)p1.x * D + c);
        float w0 = __int_as_float(p0.y);
        float w1 = __int_as_float(p1.y);
        a.x += w0 * v0.x + w1 * v1.x;
        a.y += w0 * v0.y + w1 * v1.y;
        a.z += w0 * v0.z + w1 * v1.z;
        a.w += w0 * v0.w + w1 * v1.w;
    }
    if (i < end) {
        int2 p = g_edge[i];
        float4 v = *(const float4*)(x + (size_t)p.x * D + c);
        float ww = __int_as_float(p.y);
        a.x += ww * v.x; a.y += ww * v.y; a.z += ww * v.z; a.w += ww * v.w;
    }
    return a;
}

// Dense SpMM over all nodes. flip=0: g_x -> g_y; flip=1: g_y -> g_x.
__global__ void spmm_dense_kernel(int n_nodes, int flip) {
    const float* __restrict__ x = flip ? g_y : g_x;
    float*                    y = flip ? g_x : g_y;
    int t = blockIdx.x * blockDim.x + threadIdx.x;
    int node = t >> 4;
    if (node >= n_nodes) return;
    int c = (t & 15) << 2;
    float4 a = row_gather(x, node, c);
    *(float4*)(y + (size_t)node * D + c) = a;   // full overwrite
}

// Sparse-output SpMM (layer 3): g_x (x2) -> g_b3, only sampled rows.
// Duplicate rows write identical data — benign.
__global__ void spmm_list_kernel(const int* __restrict__ users,
                                 const int* __restrict__ items,
                                 int B, int n_users) {
    int t = blockIdx.x * blockDim.x + threadIdx.x;
    int li = t >> 4;
    if (li >= 2 * B) return;
    int node = (li < B) ? users[li] : n_users + items[li - B];
    int c = (t & 15) << 2;
    float4 a = row_gather(g_x, node, c);
    *(float4*)(g_b3 + (size_t)node * D + c) = a;
}

// One warp per (user, item) pair. Final row = (x0+x1+x2+x3)/4 on the fly
// from ue/ie, g_y(x1), g_x(x2), g_b3(x3). 1/16 folded into the dot.
__global__ void score_kernel(const float* __restrict__ ue,
                             const float* __restrict__ ie,
                             const int* __restrict__ users,
                             const int* __restrict__ items,
                             float* __restrict__ out, int B, int n_users) {
    int g    = blockIdx.x * blockDim.x + threadIdx.x;
    int pair = g >> 5;
    int lane = threadIdx.x & 31;
    if (pair >= B) return;
    int un = users[pair];
    int in = items[pair];
    int ir = n_users + in;
    size_t uo = (size_t)un * D;
    size_t io = (size_t)ir * D;
    float2 u0 = ((const float2*)(ue + uo))[lane];
    float2 u1 = ((const float2*)(g_y + uo))[lane];
    float2 u2 = ((const float2*)(g_x + uo))[lane];
    float2 u3 = ((const float2*)(g_b3 + uo))[lane];
    float2 v0 = ((const float2*)(ie + (size_t)in * D))[lane];
    float2 v1 = ((const float2*)(g_y + io))[lane];
    float2 v2 = ((const float2*)(g_x + io))[lane];
    float2 v3 = ((const float2*)(g_b3 + io))[lane];
    float ux = u0.x + u1.x + u2.x + u3.x;
    float uy = u0.y + u1.y + u2.y + u3.y;
    float vx = v0.x + v1.x + v2.x + v3.x;
    float vy = v0.y + v1.y + v2.y + v3.y;
    float s = ux * vx + uy * vy;
    #pragma unroll
    for (int o = 16; o; o >>= 1) s += __shfl_xor_sync(0xffffffffu, s, o);
    if (lane == 0) out[pair] = s * (1.0f / 16.0f);
}

extern "C" void kernel_launch(void* const* d_in, const int* in_sizes, int n_in,
                              void* d_out, int out_size) {
    const float* ue    = (const float*)d_in[0];
    const float* ie    = (const float*)d_in[1];
    const int*   esrc  = (const int*)  d_in[2];
    const int*   edst  = (const int*)  d_in[3];
    const float* ew    = (const float*)d_in[4];
    const int*   users = (const int*)  d_in[5];
    const int*   items = (const int*)  d_in[6];

    int n_user_f  = in_sizes[0];
    int n_item_f  = in_sizes[1];
    int n_edges   = in_sizes[2];
    int B         = in_sizes[5];
    int n_total_f = n_user_f + n_item_f;
    int n_users   = n_user_f / D;
    int n_nodes   = n_total_f / D;
    int n4        = n_total_f >> 2;

    init_kernel<<<(n4 + 255) / 256, 256>>>(ue, ie, n_user_f, n4, n_nodes);
    bucket_kernel<<<(n_edges + 255) / 256, 256>>>(esrc, edst, ew, n_edges);

    long long td = (long long)n_nodes * 16;
    int gd = (int)((td + 255) / 256);
    // Layer 1: x1 = A x0   (g_x -> g_y)
    spmm_dense_kernel<<<gd, 256>>>(n_nodes, 0);
    // Layer 2: x2 = A x1   (g_y -> g_x)
    spmm_dense_kernel<<<gd, 256>>>(n_nodes, 1);
    // Layer 3: x3 = A x2 only at sampled rows (g_x -> g_b3)
    int gl = (2 * B * 16 + 255) / 256;
    spmm_list_kernel<<<gl, 256>>>(users, items, B, n_users);

    score_kernel<<<(B * 32 + 255) / 256, 256>>>(ue, ie, users, items,
                                                (float*)d_out, B, n_users);
}

// round 8
// speedup vs baseline: 1.1087x; 1.1087x over previous
#include <cuda_runtime.h>

#define D 64
#define MAX_NODES 150016
#define MAX_EDGES 2100000
#define SCAN_B 512
#define MAX_BLKS ((MAX_NODES + SCAN_B - 1) / SCAN_B)

// Static scratch (allocation-free rule). Kernels bind these symbols directly;
// never passed from host as kernel args (host-side decay bug, R4).
__device__ float g_x[(size_t)MAX_NODES * D];    // x0 concat, later x2
__device__ float g_y[(size_t)MAX_NODES * D];    // x1
__device__ float g_b3[(size_t)MAX_NODES * D];   // x3 (sampled rows only)
__device__ int   g_cnt[MAX_NODES];              // per-dst edge counts
__device__ int   g_off[MAX_NODES + 1];          // CSR offsets
__device__ int   g_cur[MAX_NODES];              // scatter cursors
__device__ int   g_bsum[MAX_BLKS];              // per-block sums for scan
__device__ int2  g_edge[MAX_EDGES];             // dst-grouped packed (src, w-bits)

// Concatenate user/item embeddings into g_x (x0); zero the histogram counts.
__global__ void init_kernel(const float* __restrict__ ue,
                            const float* __restrict__ ie,
                            int n_user_f, int n4, int n_nodes) {
    int i = blockIdx.x * blockDim.x + threadIdx.x;   // float4 index
    if (i < n_nodes) g_cnt[i] = 0;
    if (i >= n4) return;
    int f = i << 2;
    float4 v = (f < n_user_f) ? ((const float4*)ue)[i]
                              : ((const float4*)ie)[i - (n_user_f >> 2)];
    ((float4*)g_x)[i] = v;
}

__global__ void hist_kernel(const int* __restrict__ dst, int n_edges) {
    int e = blockIdx.x * blockDim.x + threadIdx.x;
    if (e < n_edges) atomicAdd(&g_cnt[dst[e]], 1);
}

// Block-wide inclusive scan of one int per thread (SCAN_B threads).
__device__ __forceinline__ int block_incl_scan(int v) {
    __shared__ int wsum[SCAN_B / 32];
    int lane = threadIdx.x & 31;
    int wid  = threadIdx.x >> 5;
    int x = v;
    #pragma unroll
    for (int o = 1; o < 32; o <<= 1) {
        int t = __shfl_up_sync(0xffffffffu, x, o);
        if (lane >= o) x += t;
    }
    if (lane == 31) wsum[wid] = x;
    __syncthreads();
    if (wid == 0) {
        int w = (lane < SCAN_B / 32) ? wsum[lane] : 0;
        #pragma unroll
        for (int o = 1; o < SCAN_B / 32; o <<= 1) {
            int t = __shfl_up_sync(0xffffffffu, w, o);
            if (lane >= o) w += t;
        }
        if (lane < SCAN_B / 32) wsum[lane] = w;
    }
    __syncthreads();
    return x + (wid ? wsum[wid - 1] : 0);
}

__global__ void scanA_kernel(int n) {
    int i = blockIdx.x * SCAN_B + threadIdx.x;
    int v = (i < n) ? g_cnt[i] : 0;
    int inc = block_incl_scan(v);
    if (i < n) g_off[i] = inc - v;
    if (threadIdx.x == SCAN_B - 1) g_bsum[blockIdx.x] = inc;
}

__global__ void scanB_kernel(int nblk, int n) {
    int v = (threadIdx.x < nblk) ? g_bsum[threadIdx.x] : 0;
    int inc = block_incl_scan(v);
    if (threadIdx.x < nblk) g_bsum[threadIdx.x] = inc - v;
    if (threadIdx.x == SCAN_B - 1) g_off[n] = inc;
}

__global__ void scanC_kernel(int n) {
    int i = blockIdx.x * SCAN_B + threadIdx.x;
    if (i < n) {
        int o = g_off[i] + g_bsum[blockIdx.x];
        g_off[i] = o;
        g_cur[i] = o;
    }
}

__global__ void scatter_kernel(const int* __restrict__ src,
                               const int* __restrict__ dst,
                               const float* __restrict__ w, int n_edges) {
    int e = blockIdx.x * blockDim.x + threadIdx.x;
    if (e >= n_edges) return;
    int d = dst[e];
    int pos = atomicAdd(&g_cur[d], 1);
    g_edge[pos] = make_int2(src[e], __float_as_int(w[e]));
}

// Row-gather accumulate for one (node, c) slice, 4-deep unroll: keeps 4
// independent edge loads + 4 gather loads in flight (latency-bound kernel).
__device__ __forceinline__ float4 row_gather(const float* __restrict__ x,
                                             int node, int c) {
    int beg = g_off[node];
    int end = g_off[node + 1];
    float4 a = make_float4(0.f, 0.f, 0.f, 0.f);
    int i = beg;
    for (; i + 4 <= end; i += 4) {
        int2 p0 = g_edge[i];
        int2 p1 = g_edge[i + 1];
        int2 p2 = g_edge[i + 2];
        int2 p3 = g_edge[i + 3];
        float4 v0 = *(const float4*)(x + (size_t)p0.x * D + c);
        float4 v1 = *(const float4*)(x + (size_t)p1.x * D + c);
        float4 v2 = *(const float4*)(x + (size_t)p2.x * D + c);
        float4 v3 = *(const float4*)(x + (size_t)p3.x * D + c);
        float w0 = __int_as_float(p0.y);
        float w1 = __int_as_float(p1.y);
        float w2 = __int_as_float(p2.y);
        float w3 = __int_as_float(p3.y);
        a.x += w0 * v0.x + w1 * v1.x + w2 * v2.x + w3 * v3.x;
        a.y += w0 * v0.y + w1 * v1.y + w2 * v2.y + w3 * v3.y;
        a.z += w0 * v0.z + w1 * v1.z + w2 * v2.z + w3 * v3.z;
        a.w += w0 * v0.w + w1 * v1.w + w2 * v2.w + w3 * v3.w;
    }
    for (; i < end; i++) {
        int2 p = g_edge[i];
        float4 v = *(const float4*)(x + (size_t)p.x * D + c);
        float ww = __int_as_float(p.y);
        a.x += ww * v.x; a.y += ww * v.y; a.z += ww * v.z; a.w += ww * v.w;
    }
    return a;
}

// Dense SpMM over all nodes. flip=0: g_x -> g_y; flip=1: g_y -> g_x.
__global__ void spmm_dense_kernel(int n_nodes, int flip) {
    const float* __restrict__ x = flip ? g_y : g_x;
    float*                    y = flip ? g_x : g_y;
    int t = blockIdx.x * blockDim.x + threadIdx.x;
    int node = t >> 4;
    if (node >= n_nodes) return;
    int c = (t & 15) << 2;
    float4 a = row_gather(x, node, c);
    *(float4*)(y + (size_t)node * D + c) = a;   // full overwrite
}

// Sparse-output SpMM (layer 3): g_x (x2) -> g_b3, only sampled rows.
// Duplicate rows write identical data — benign.
__global__ void spmm_list_kernel(const int* __restrict__ users,
                                 const int* __restrict__ items,
                                 int B, int n_users) {
    int t = blockIdx.x * blockDim.x + threadIdx.x;
    int li = t >> 4;
    if (li >= 2 * B) return;
    int node = (li < B) ? users[li] : n_users + items[li - B];
    int c = (t & 15) << 2;
    float4 a = row_gather(g_x, node, c);
    *(float4*)(g_b3 + (size_t)node * D + c) = a;
}

// One warp per (user, item) pair. Final row = (x0+x1+x2+x3)/4 on the fly
// from ue/ie, g_y(x1), g_x(x2), g_b3(x3). 1/16 folded into the dot.
__global__ void score_kernel(const float* __restrict__ ue,
                             const float* __restrict__ ie,
                             const int* __restrict__ users,
                             const int* __restrict__ items,
                             float* __restrict__ out, int B, int n_users) {
    int g    = blockIdx.x * blockDim.x + threadIdx.x;
    int pair = g >> 5;
    int lane = threadIdx.x & 31;
    if (pair >= B) return;
    int un = users[pair];
    int in = items[pair];
    int ir = n_users + in;
    size_t uo = (size_t)un * D;
    size_t io = (size_t)ir * D;
    float2 u0 = ((const float2*)(ue + uo))[lane];
    float2 u1 = ((const float2*)(g_y + uo))[lane];
    float2 u2 = ((const float2*)(g_x + uo))[lane];
    float2 u3 = ((const float2*)(g_b3 + uo))[lane];
    float2 v0 = ((const float2*)(ie + (size_t)in * D))[lane];
    float2 v1 = ((const float2*)(g_y + io))[lane];
    float2 v2 = ((const float2*)(g_x + io))[lane];
    float2 v3 = ((const float2*)(g_b3 + io))[lane];
    float ux = u0.x + u1.x + u2.x + u3.x;
    float uy = u0.y + u1.y + u2.y + u3.y;
    float vx = v0.x + v1.x + v2.x + v3.x;
    float vy = v0.y + v1.y + v2.y + v3.y;
    float s = ux * vx + uy * vy;
    #pragma unroll
    for (int o = 16; o; o >>= 1) s += __shfl_xor_sync(0xffffffffu, s, o);
    if (lane == 0) out[pair] = s * (1.0f / 16.0f);
}

extern "C" void kernel_launch(void* const* d_in, const int* in_sizes, int n_in,
                              void* d_out, int out_size) {
    const float* ue    = (const float*)d_in[0];
    const float* ie    = (const float*)d_in[1];
    const int*   esrc  = (const int*)  d_in[2];
    const int*   edst  = (const int*)  d_in[3];
    const float* ew    = (const float*)d_in[4];
    const int*   users = (const int*)  d_in[5];
    const int*   items = (const int*)  d_in[6];

    int n_user_f  = in_sizes[0];
    int n_item_f  = in_sizes[1];
    int n_edges   = in_sizes[2];
    int B         = in_sizes[5];
    int n_total_f = n_user_f + n_item_f;
    int n_users   = n_user_f / D;
    int n_nodes   = n_total_f / D;
    int n4        = n_total_f >> 2;
    int nblk      = (n_nodes + SCAN_B - 1) / SCAN_B;

    init_kernel<<<(n4 + 255) / 256, 256>>>(ue, ie, n_user_f, n4, n_nodes);
    hist_kernel<<<(n_edges + 255) / 256, 256>>>(edst, n_edges);
    scanA_kernel<<<nblk, SCAN_B>>>(n_nodes);
    scanB_kernel<<<1, SCAN_B>>>(nblk, n_nodes);
    scanC_kernel<<<nblk, SCAN_B>>>(n_nodes);
    scatter_kernel<<<(n_edges + 255) / 256, 256>>>(esrc, edst, ew, n_edges);

    long long td = (long long)n_nodes * 16;
    int gd = (int)((td + 255) / 256);
    // Layer 1: x1 = A x0   (g_x -> g_y)
    spmm_dense_kernel<<<gd, 256>>>(n_nodes, 0);
    // Layer 2: x2 = A x1   (g_y -> g_x)
    spmm_dense_kernel<<<gd, 256>>>(n_nodes, 1);
    // Layer 3: x3 = A x2 only at sampled rows (g_x -> g_b3)
    int gl = (2 * B * 16 + 255) / 256;
    spmm_list_kernel<<<gl, 256>>>(users, items, B, n_users);

    score_kernel<<<(B * 32 + 255) / 256, 256>>>(ue, ie, users, items,
                                                (float*)d_out, B, n_users);
}